// round 15
// baseline (speedup 1.0000x reference)
#include <cuda_runtime.h>
#include <cstdint>

// ---------------------------------------------------------------------------
// VectorQuantizer — fused BF16 tensor filter + bit-exact rescue (one kernel).
//   Exact semantics (validated R6..R13): m = exact fp32 FFMA dot (ascending),
//   c = butterfly ||z||^2, d2 = fl(fma(m,-2,c)) + e2, argmin = first index,
//   q_st = fl(z + fl(q - z)).
//   Filter: mma.m16n8k16.bf16 proxy; per-128-code chunk min via chunk-max(m~).
//   Rescue: chunks with proxy <= gmin + 2E, E = s1*emax*2^-6 + 1e-5.
// R14: filter+resolve+loss fused per-CTA (proxies in smem, no d_chmin
//   round-trip, no cross-CTA deps, last-CTA loss reduce); fixed local-memory
//   demotion of zv (dynamic index removed from epilogue).
// ---------------------------------------------------------------------------

#define N_ROWS  32768
#define CDIM    32
#define KCODES  8192
#define NCHUNK  64            // 64 chunks x 128 codes
#define WPR     16            // bf16x2 words per row

#define CTA_T    128          // 4 warps
#define ROWS_CTA 128          // 32 rows per warp
#define GRID_M   (N_ROWS / ROWS_CTA)   // 256
#define CHM_S    66           // padded chunk-min row stride (even, conflict-free)

__device__ __align__(16) unsigned d_zpackb[N_ROWS * WPR];  // bf16x2 frag words
__device__ __align__(16) unsigned d_epackb[KCODES * WPR];  // bf16x2 frag words
__device__ __align__(16) float d_eT[CDIM * KCODES];        // eT[i][k] exact fp32
__device__ __align__(16) float d_e2[KCODES];               // butterfly ||e||^2
__device__ float d_c[N_ROWS];                              // butterfly ||z||^2
__device__ float d_s1[N_ROWS];                             // sum |z_i| (bound)
__device__ int   d_emaxbits;                               // max |e| bits (idempotent)
__device__ float d_partials[GRID_M];
__device__ unsigned d_done;                                // self-resetting ticket

// ---- helpers --------------------------------------------------------------
__device__ __forceinline__ unsigned bf16x2_rn(float hi, float lo) {
    unsigned w;
    asm("cvt.rn.bf16x2.f32 %0, %1, %2;" : "=r"(w) : "f"(hi), "f"(lo));
    return w;
}
__device__ __forceinline__ float butterfly32(float* a) {
#pragma unroll
    for (int off = 16; off >= 1; off >>= 1)
#pragma unroll
        for (int i = 0; i < 16; i++)
            if (i < off) a[i] = __fadd_rn(a[i], a[i + off]);
    return a[0];
}
__device__ __forceinline__ void mma_bf16(float& d0, float& d1, float& d2, float& d3,
                                         unsigned a0, unsigned a1, unsigned a2, unsigned a3,
                                         unsigned b0, unsigned b1) {
    asm volatile(
        "mma.sync.aligned.m16n8k16.row.col.f32.bf16.bf16.f32 "
        "{%0,%1,%2,%3}, {%4,%5,%6,%7}, {%8,%9}, {%0,%1,%2,%3};"
        : "+f"(d0), "+f"(d1), "+f"(d2), "+f"(d3)
        : "r"(a0), "r"(a1), "r"(a2), "r"(a3), "r"(b0), "r"(b1));
}

// ---- P: merged prep (blocks 0..31 -> codes, rest -> rows) -----------------
__global__ void vq_prep(const float* __restrict__ emb, const float* __restrict__ z) {
    int b = blockIdx.x;
    if (b < KCODES / 256) {
        int k = b * 256 + threadIdx.x;
        float e[CDIM], a[CDIM];
        const float4* er = (const float4*)(emb + (size_t)k * CDIM);
        float amax = 0.f;
#pragma unroll
        for (int j = 0; j < 8; j++) {
            float4 v = er[j];
            e[4 * j] = v.x; e[4 * j + 1] = v.y; e[4 * j + 2] = v.z; e[4 * j + 3] = v.w;
        }
#pragma unroll
        for (int i = 0; i < CDIM; i++) {
            a[i] = __fmul_rn(e[i], e[i]);
            amax = fmaxf(amax, fabsf(e[i]));
        }
        d_e2[k] = butterfly32(a);
#pragma unroll
        for (int i = 0; i < CDIM; i++) d_eT[i * KCODES + k] = e[i];
#pragma unroll
        for (int p = 0; p < WPR; p++)
            d_epackb[(size_t)k * WPR + (p & 3) * 4 + (p >> 2)] =
                bf16x2_rn(e[2 * p + 1], e[2 * p]);
#pragma unroll
        for (int off = 16; off >= 1; off >>= 1)
            amax = fmaxf(amax, __shfl_xor_sync(0xffffffffu, amax, off));
        if ((threadIdx.x & 31) == 0)
            atomicMax(&d_emaxbits, __float_as_int(amax));
    } else {
        int n = (b - KCODES / 256) * 256 + threadIdx.x;
        float zv[CDIM], a[CDIM];
        const float4* zr = (const float4*)(z + (size_t)n * CDIM);
        float s1 = 0.f;
#pragma unroll
        for (int j = 0; j < 8; j++) {
            float4 v = zr[j];
            zv[4 * j] = v.x; zv[4 * j + 1] = v.y; zv[4 * j + 2] = v.z; zv[4 * j + 3] = v.w;
        }
#pragma unroll
        for (int i = 0; i < CDIM; i++) {
            a[i] = __fmul_rn(zv[i], zv[i]);
            s1 += fabsf(zv[i]);
        }
        d_c[n] = butterfly32(a);
        d_s1[n] = s1;
#pragma unroll
        for (int p = 0; p < WPR; p++)
            d_zpackb[(size_t)n * WPR + (p & 3) * 4 + (p >> 2)] =
                bf16x2_rn(zv[2 * p + 1], zv[2 * p]);
    }
}

// ---- fused main: filter (all 64 chunks) + resolve + output + loss ---------
__global__ __launch_bounds__(CTA_T) void vq_main(const float* __restrict__ z,
                                                 const float* __restrict__ emb,
                                                 float* __restrict__ out) {
    __shared__ uint4 s_b[512];                   // B words for one chunk (8 KB)
    __shared__ float s_chmin[ROWS_CTA * CHM_S];  // per-row chunk-min proxies
    __shared__ float warpsum[4];
    __shared__ int   s_last;

    int tid  = threadIdx.x;
    int lane = tid & 31;
    int wid  = tid >> 5;           // 0..3
    int gid  = lane >> 2;
    int tig  = lane & 3;
    int rowbase = blockIdx.x * ROWS_CTA + wid * 32;
    int rlbase  = wid * 32;

    // ---- phase 1: filter ----
    uint4 A[2][2];
#pragma unroll
    for (int t = 0; t < 2; t++) {
        int r0 = rowbase + t * 16 + gid;
        A[t][0] = *(const uint4*)(d_zpackb + (size_t)r0 * WPR + tig * 4);
        A[t][1] = *(const uint4*)(d_zpackb + (size_t)(r0 + 8) * WPR + tig * 4);
    }
    float c0[2], c1[2];
#pragma unroll
    for (int t = 0; t < 2; t++) {
        c0[t] = d_c[rowbase + t * 16 + gid];
        c1[t] = d_c[rowbase + t * 16 + gid + 8];
    }

    for (int ch = 0; ch < NCHUNK; ch++) {
        for (int j = tid; j < 512; j += CTA_T) {
            int q = j >> 5, ln = j & 31;
            s_b[j] = *(const uint4*)(d_epackb +
                (size_t)(ch * 128 + q * 8 + (ln >> 2)) * WPR + (ln & 3) * 4);
        }
        __syncthreads();

        float ninf = __int_as_float(0xff800000);
        float mx[2][2] = {{ninf, ninf}, {ninf, ninf}};
#pragma unroll 4
        for (int q = 0; q < 16; q++) {
            uint4 B = s_b[q * 32 + lane];
#pragma unroll
            for (int t = 0; t < 2; t++) {
                float d0 = 0.f, d1 = 0.f, d2 = 0.f, d3 = 0.f;
                mma_bf16(d0, d1, d2, d3, A[t][0].x, A[t][1].x, A[t][0].y, A[t][1].y, B.x, B.y);
                mma_bf16(d0, d1, d2, d3, A[t][0].z, A[t][1].z, A[t][0].w, A[t][1].w, B.z, B.w);
                mx[t][0] = fmaxf(mx[t][0], fmaxf(d0, d1));
                mx[t][1] = fmaxf(mx[t][1], fmaxf(d2, d3));
            }
        }
#pragma unroll
        for (int t = 0; t < 2; t++)
#pragma unroll
            for (int h = 0; h < 2; h++) {
                float v = mx[t][h];
                v = fmaxf(v, __shfl_xor_sync(0xffffffffu, v, 1));
                v = fmaxf(v, __shfl_xor_sync(0xffffffffu, v, 2));
                if (tig == 0) {
                    int rl = rlbase + t * 16 + h * 8 + gid;
                    float cc = h ? c1[t] : c0[t];
                    s_chmin[rl * CHM_S + ch] = __fmaf_rn(v, -2.0f, cc);
                }
            }
        __syncthreads();
    }

    // ---- phase 2: resolve (warp-private rows; smem written by same warp) ----
    float emax = __int_as_float(d_emaxbits);
    float lossacc = 0.f;

    for (int r = 0; r < 32; r++) {
        int rl  = rlbase + r;
        int row = blockIdx.x * ROWS_CTA + rl - rlbase + rlbase;  // = cta*128+rl
        row = blockIdx.x * ROWS_CTA + rl;

        float2 cm = *(const float2*)(s_chmin + rl * CHM_S + 2 * lane);
        float g = fminf(cm.x, cm.y);
#pragma unroll
        for (int off = 16; off >= 1; off >>= 1)
            g = fminf(g, __shfl_xor_sync(0xffffffffu, g, off));

        float E = __fmaf_rn(d_s1[row], emax * 0.015625f /*2^-6*/, 1e-5f);
        float thresh = g + 2.0f * E;
        unsigned msk0 = __ballot_sync(0xffffffffu, cm.x <= thresh);
        unsigned msk1 = __ballot_sync(0xffffffffu, cm.y <= thresh);

        float zv[CDIM];                       // register-resident (no dyn index)
        const float4* zr = (const float4*)(z + (size_t)row * CDIM);
#pragma unroll
        for (int j = 0; j < 8; j++) {
            float4 v = zr[j];
            zv[4 * j] = v.x; zv[4 * j + 1] = v.y;
            zv[4 * j + 2] = v.z; zv[4 * j + 3] = v.w;
        }
        float c = d_c[row];

        unsigned long long key = 0xFFFFFFFFFFFFFFFFull;
        while (msk0 | msk1) {
            int ch;
            if (msk0) { int l = __ffs(msk0) - 1; msk0 &= msk0 - 1; ch = 2 * l; }
            else      { int l = __ffs(msk1) - 1; msk1 &= msk1 - 1; ch = 2 * l + 1; }

            float4 e2v = ((const float4*)(d_e2 + ch * 128))[lane];
            float m0 = 0.f, m1 = 0.f, m2 = 0.f, m3 = 0.f;
#pragma unroll
            for (int i = 0; i < CDIM; i++) {  // exact ascending FFMA chains
                float4 ev = ((const float4*)(d_eT + (size_t)i * KCODES + ch * 128))[lane];
                m0 = __fmaf_rn(zv[i], ev.x, m0);
                m1 = __fmaf_rn(zv[i], ev.y, m1);
                m2 = __fmaf_rn(zv[i], ev.z, m2);
                m3 = __fmaf_rn(zv[i], ev.w, m3);
            }
            int k0 = ch * 128 + lane * 4;
            float da = __fadd_rn(__fmaf_rn(m0, -2.0f, c), e2v.x);
            float db = __fadd_rn(__fmaf_rn(m1, -2.0f, c), e2v.y);
            float dc = __fadd_rn(__fmaf_rn(m2, -2.0f, c), e2v.z);
            float dd = __fadd_rn(__fmaf_rn(m3, -2.0f, c), e2v.w);
            unsigned long long ka = ((unsigned long long)__float_as_uint(da) << 13) | (unsigned)k0;
            unsigned long long kb = ((unsigned long long)__float_as_uint(db) << 13) | (unsigned)(k0 + 1);
            unsigned long long kc = ((unsigned long long)__float_as_uint(dc) << 13) | (unsigned)(k0 + 2);
            unsigned long long kd = ((unsigned long long)__float_as_uint(dd) << 13) | (unsigned)(k0 + 3);
            ka = ka < kb ? ka : kb;
            kc = kc < kd ? kc : kd;
            ka = ka < kc ? ka : kc;
            key = key < ka ? key : ka;
        }
#pragma unroll
        for (int off = 16; off >= 1; off >>= 1) {
            unsigned long long o = __shfl_xor_sync(0xffffffffu, key, off);
            if (o < key) key = o;
        }
        int k = (int)(key & 0x1FFFull);

        // epilogue: lanes 0..7, fresh float4 loads (keeps zv in registers)
        if (lane < 8) {
            float4 e = ((const float4*)(emb + (size_t)k * CDIM))[lane];
            float4 zq = ((const float4*)(z + (size_t)row * CDIM))[lane];
            float dx = __fadd_rn(e.x, -zq.x), dy = __fadd_rn(e.y, -zq.y);
            float dz = __fadd_rn(e.z, -zq.z), dw = __fadd_rn(e.w, -zq.w);
            float4 qv;
            qv.x = __fadd_rn(zq.x, dx); qv.y = __fadd_rn(zq.y, dy);
            qv.z = __fadd_rn(zq.z, dz); qv.w = __fadd_rn(zq.w, dw);
            ((float4*)(out + (size_t)row * CDIM))[lane] = qv;
            lossacc += dx * dx + dy * dy + dz * dz + dw * dw;
            if (lane == 0) out[(size_t)N_ROWS * CDIM + 2 + row] = (float)k;
        }
    }

    // ---- loss: warp -> CTA -> last-CTA global reduce ----
#pragma unroll
    for (int off = 16; off >= 1; off >>= 1)
        lossacc += __shfl_down_sync(0xffffffffu, lossacc, off);
    if (lane == 0) warpsum[wid] = lossacc;
    __syncthreads();
    if (tid == 0) {
        float v = warpsum[0] + warpsum[1] + warpsum[2] + warpsum[3];
        d_partials[blockIdx.x] = v;
        __threadfence();
        unsigned t = atomicAdd(&d_done, 1u);
        s_last = (t == (unsigned)gridDim.x - 1u);
        if (s_last) d_done = 0u;     // self-reset for next graph replay
    }
    __syncthreads();
    if (s_last) {
        __threadfence();
        float s = d_partials[tid] + d_partials[tid + 128];
#pragma unroll
        for (int off = 16; off >= 1; off >>= 1)
            s += __shfl_down_sync(0xffffffffu, s, off);
        if (lane == 0) warpsum[wid] = s;
        __syncthreads();
        if (tid == 0) {
            float total = warpsum[0] + warpsum[1] + warpsum[2] + warpsum[3];
            float loss = total / (float)(N_ROWS * CDIM);
            out[(size_t)N_ROWS * CDIM + 0] = loss;   // vq_loss
            out[(size_t)N_ROWS * CDIM + 1] = loss;   // commitment_loss
        }
    }
}

// ---- entry ----------------------------------------------------------------
extern "C" void kernel_launch(void* const* d_in, const int* in_sizes, int n_in,
                              void* d_out, int out_size) {
    const float* z   = (const float*)d_in[0];
    const float* emb = (const float*)d_in[1];
    if (n_in >= 2 && in_sizes[0] == KCODES * CDIM && in_sizes[1] == N_ROWS * CDIM) {
        const float* t = z; z = emb; emb = t;
    }
    float* out = (float*)d_out;

    vq_prep<<<KCODES / 256 + N_ROWS / 256, 256>>>(emb, z);
    vq_main<<<GRID_M, CTA_T>>>(z, emb, out);
    (void)out_size;
}

// round 17
// speedup vs baseline: 2.4042x; 2.4042x over previous
#include <cuda_runtime.h>
#include <cstdint>

// ---------------------------------------------------------------------------
// VectorQuantizer — BF16 tensor-core filter + bit-exact rescue (R13 structure).
//   Exact semantics (validated R6..R13): m = exact fp32 FFMA dot (ascending),
//   c = butterfly ||z||^2, d2 = fl(fma(m,-2,c)) + e2, argmin = first index,
//   q_st = fl(z + fl(q - z)).
//   Filter: mma.m16n8k16.bf16 proxy; per-128-code chunk min via chunk-max(m~).
//   Rescue: chunks with proxy <= gmin + 2E, E = s1*emax*2^-6 + 1e-5.
// R16: (a) resolve epilogue no longer dynamically indexes zv -> zv stays in
//   registers (was demoted to local memory since R12, poisoning the rescore
//   FFMA chains with LDL); (b) filter B staging double-buffered.
// ---------------------------------------------------------------------------

#define N_ROWS  32768
#define CDIM    32
#define KCODES  8192
#define NCHUNK  64            // 64 chunks x 128 codes
#define WPR     16            // bf16x2 words per row

#define NSPLIT_F 4            // filter code-splits (latency hiding)
#define ROWBLK_F 128          // 32768 / 256 rows per CTA

__device__ __align__(16) unsigned d_zpackb[N_ROWS * WPR];  // bf16x2 frag words
__device__ __align__(16) unsigned d_epackb[KCODES * WPR];  // bf16x2 frag words
__device__ __align__(16) float d_eT[CDIM * KCODES];        // eT[i][k] exact fp32
__device__ __align__(16) float d_e2[KCODES];               // butterfly ||e||^2
__device__ float d_c[N_ROWS];                              // butterfly ||z||^2
__device__ float d_s1[N_ROWS];                             // sum |z_i| (bound)
__device__ float d_chmin[(size_t)N_ROWS * NCHUNK];         // proxy chunk mins
__device__ int   d_emaxbits;                               // max |e| as int bits
__device__ float d_partials[4096];

// ---- helpers --------------------------------------------------------------
__device__ __forceinline__ unsigned bf16x2_rn(float hi, float lo) {
    unsigned w;
    asm("cvt.rn.bf16x2.f32 %0, %1, %2;" : "=r"(w) : "f"(hi), "f"(lo));
    return w;
}
__device__ __forceinline__ float butterfly32(float* a) {
#pragma unroll
    for (int off = 16; off >= 1; off >>= 1)
#pragma unroll
        for (int i = 0; i < 16; i++)
            if (i < off) a[i] = __fadd_rn(a[i], a[i + off]);
    return a[0];
}
__device__ __forceinline__ void mma_bf16(float& d0, float& d1, float& d2, float& d3,
                                         unsigned a0, unsigned a1, unsigned a2, unsigned a3,
                                         unsigned b0, unsigned b1) {
    asm volatile(
        "mma.sync.aligned.m16n8k16.row.col.f32.bf16.bf16.f32 "
        "{%0,%1,%2,%3}, {%4,%5,%6,%7}, {%8,%9}, {%0,%1,%2,%3};"
        : "+f"(d0), "+f"(d1), "+f"(d2), "+f"(d3)
        : "r"(a0), "r"(a1), "r"(a2), "r"(a3), "r"(b0), "r"(b1));
}

// ---- P: merged prep (blocks 0..31 -> codes, rest -> rows) -----------------
__global__ void vq_prep(const float* __restrict__ emb, const float* __restrict__ z) {
    int b = blockIdx.x;
    if (b < KCODES / 256) {
        int k = b * 256 + threadIdx.x;
        float e[CDIM], a[CDIM];
        const float4* er = (const float4*)(emb + (size_t)k * CDIM);
        float amax = 0.f;
#pragma unroll
        for (int j = 0; j < 8; j++) {
            float4 v = er[j];
            e[4 * j] = v.x; e[4 * j + 1] = v.y; e[4 * j + 2] = v.z; e[4 * j + 3] = v.w;
        }
#pragma unroll
        for (int i = 0; i < CDIM; i++) {
            a[i] = __fmul_rn(e[i], e[i]);
            amax = fmaxf(amax, fabsf(e[i]));
        }
        d_e2[k] = butterfly32(a);
#pragma unroll
        for (int i = 0; i < CDIM; i++) d_eT[i * KCODES + k] = e[i];
#pragma unroll
        for (int p = 0; p < WPR; p++)
            d_epackb[(size_t)k * WPR + (p & 3) * 4 + (p >> 2)] =
                bf16x2_rn(e[2 * p + 1], e[2 * p]);
#pragma unroll
        for (int off = 16; off >= 1; off >>= 1)
            amax = fmaxf(amax, __shfl_xor_sync(0xffffffffu, amax, off));
        if ((threadIdx.x & 31) == 0)
            atomicMax(&d_emaxbits, __float_as_int(amax));
    } else {
        int n = (b - KCODES / 256) * 256 + threadIdx.x;
        float zv[CDIM], a[CDIM];
        const float4* zr = (const float4*)(z + (size_t)n * CDIM);
        float s1 = 0.f;
#pragma unroll
        for (int j = 0; j < 8; j++) {
            float4 v = zr[j];
            zv[4 * j] = v.x; zv[4 * j + 1] = v.y; zv[4 * j + 2] = v.z; zv[4 * j + 3] = v.w;
        }
#pragma unroll
        for (int i = 0; i < CDIM; i++) {
            a[i] = __fmul_rn(zv[i], zv[i]);
            s1 += fabsf(zv[i]);
        }
        d_c[n] = butterfly32(a);
        d_s1[n] = s1;
#pragma unroll
        for (int p = 0; p < WPR; p++)
            d_zpackb[(size_t)n * WPR + (p & 3) * 4 + (p >> 2)] =
                bf16x2_rn(zv[2 * p + 1], zv[2 * p]);
    }
}

// ---- filter: BF16 mma proxy, double-buffered B staging --------------------
// CTA: 256 thr = 8 warps x 32 rows. Grid: 128 rowblocks x NSPLIT_F.
__global__ __launch_bounds__(256) void vq_filter() {
    __shared__ uint4 s_b[2][512];   // double-buffered B words (16 KB)

    int tid  = threadIdx.x;
    int lane = tid & 31;
    int wid  = tid >> 5;
    int gid  = lane >> 2;
    int tig  = lane & 3;
    int sp   = blockIdx.x / ROWBLK_F;
    int rb   = blockIdx.x % ROWBLK_F;
    int rowbase = rb * 256 + wid * 32;

    int ch_lo = sp * (NCHUNK / NSPLIT_F);
    int ch_hi = ch_lo + NCHUNK / NSPLIT_F;

    // A fragments: [tile][rowhalf] one uint4 = both k-chunks
    uint4 A[2][2];
#pragma unroll
    for (int t = 0; t < 2; t++) {
        int r0 = rowbase + t * 16 + gid;
        A[t][0] = *(const uint4*)(d_zpackb + (size_t)r0 * WPR + tig * 4);
        A[t][1] = *(const uint4*)(d_zpackb + (size_t)(r0 + 8) * WPR + tig * 4);
    }
    float c0[2], c1[2];
#pragma unroll
    for (int t = 0; t < 2; t++) {
        c0[t] = d_c[rowbase + t * 16 + gid];
        c1[t] = d_c[rowbase + t * 16 + gid + 8];
    }

    // stage first chunk into buffer 0
    {
        int q = tid >> 5, ln = tid & 31;
        s_b[0][tid]       = *(const uint4*)(d_epackb +
            (size_t)(ch_lo * 128 + q * 8 + (ln >> 2)) * WPR + (ln & 3) * 4);
        s_b[0][tid + 256] = *(const uint4*)(d_epackb +
            (size_t)(ch_lo * 128 + (q + 8) * 8 + (ln >> 2)) * WPR + (ln & 3) * 4);
    }
    __syncthreads();

    for (int ch = ch_lo; ch < ch_hi; ch++) {
        int buf = (ch - ch_lo) & 1;
        if (ch + 1 < ch_hi) {        // prefetch next chunk into the other buffer
            int q = tid >> 5, ln = tid & 31;
            s_b[buf ^ 1][tid]       = *(const uint4*)(d_epackb +
                (size_t)((ch + 1) * 128 + q * 8 + (ln >> 2)) * WPR + (ln & 3) * 4);
            s_b[buf ^ 1][tid + 256] = *(const uint4*)(d_epackb +
                (size_t)((ch + 1) * 128 + (q + 8) * 8 + (ln >> 2)) * WPR + (ln & 3) * 4);
        }

        float ninf = __int_as_float(0xff800000);
        float mx[2][2] = {{ninf, ninf}, {ninf, ninf}};
#pragma unroll 4
        for (int q = 0; q < 16; q++) {
            uint4 B = s_b[buf][q * 32 + lane];
#pragma unroll
            for (int t = 0; t < 2; t++) {
                float d0 = 0.f, d1 = 0.f, d2 = 0.f, d3 = 0.f;
                mma_bf16(d0, d1, d2, d3, A[t][0].x, A[t][1].x, A[t][0].y, A[t][1].y, B.x, B.y);
                mma_bf16(d0, d1, d2, d3, A[t][0].z, A[t][1].z, A[t][0].w, A[t][1].w, B.z, B.w);
                mx[t][0] = fmaxf(mx[t][0], fmaxf(d0, d1));
                mx[t][1] = fmaxf(mx[t][1], fmaxf(d2, d3));
            }
        }
        // quad-reduce max m~ -> chunk-min proxy p = fl(fma(maxm,-2,c))
#pragma unroll
        for (int t = 0; t < 2; t++)
#pragma unroll
            for (int h = 0; h < 2; h++) {
                float v = mx[t][h];
                v = fmaxf(v, __shfl_xor_sync(0xffffffffu, v, 1));
                v = fmaxf(v, __shfl_xor_sync(0xffffffffu, v, 2));
                if (tig == 0) {
                    int row = rowbase + t * 16 + h * 8 + gid;
                    float cc = h ? c1[t] : c0[t];
                    d_chmin[(size_t)row * NCHUNK + ch] = __fmaf_rn(v, -2.0f, cc);
                }
            }
        __syncthreads();   // staging of buf^1 done + all reads of buf done
    }
}

// ---- resolve + output: exact rescore of rescued chunks, fused epilogue ----
// One warp per row; CTA 256 thr = 8 rows; grid 4096.
__global__ __launch_bounds__(256) void vq_resolve(const float* __restrict__ z,
                                                  const float* __restrict__ emb,
                                                  float* __restrict__ out) {
    __shared__ float warpsum[8];
    int lane = threadIdx.x & 31;
    int warp = threadIdx.x >> 5;
    int row  = blockIdx.x * 8 + warp;

    // lane l holds proxies of chunks 2l and 2l+1
    float2 cm = ((const float2*)(d_chmin + (size_t)row * NCHUNK))[lane];
    float g = fminf(cm.x, cm.y);
#pragma unroll
    for (int off = 16; off >= 1; off >>= 1)
        g = fminf(g, __shfl_xor_sync(0xffffffffu, g, off));

    float emax = __int_as_float(d_emaxbits);
    float E = __fmaf_rn(d_s1[row], emax * 0.015625f /*2^-6*/, 1e-5f);
    float thresh = g + 2.0f * E;

    unsigned msk0 = __ballot_sync(0xffffffffu, cm.x <= thresh);  // chunks 2l
    unsigned msk1 = __ballot_sync(0xffffffffu, cm.y <= thresh);  // chunks 2l+1

    float zv[CDIM];                    // static indices ONLY -> stays in regs
    const float4* zr = (const float4*)(z + (size_t)row * CDIM);
#pragma unroll
    for (int j = 0; j < 8; j++) {
        float4 v = zr[j];
        zv[4 * j] = v.x; zv[4 * j + 1] = v.y; zv[4 * j + 2] = v.z; zv[4 * j + 3] = v.w;
    }
    float c = d_c[row];

    unsigned long long key = 0xFFFFFFFFFFFFFFFFull;
    while (msk0 | msk1) {                  // uniform across warp (ballot masks)
        int ch;
        if (msk0) { int l = __ffs(msk0) - 1; msk0 &= msk0 - 1; ch = 2 * l; }
        else      { int l = __ffs(msk1) - 1; msk1 &= msk1 - 1; ch = 2 * l + 1; }

        float4 e2v = ((const float4*)(d_e2 + ch * 128))[lane];
        float m0 = 0.f, m1 = 0.f, m2 = 0.f, m3 = 0.f;
#pragma unroll
        for (int i = 0; i < CDIM; i++) {   // exact ascending FFMA chains
            float4 ev = ((const float4*)(d_eT + (size_t)i * KCODES + ch * 128))[lane];
            m0 = __fmaf_rn(zv[i], ev.x, m0);
            m1 = __fmaf_rn(zv[i], ev.y, m1);
            m2 = __fmaf_rn(zv[i], ev.z, m2);
            m3 = __fmaf_rn(zv[i], ev.w, m3);
        }
        int k0 = ch * 128 + lane * 4;
        float da = __fadd_rn(__fmaf_rn(m0, -2.0f, c), e2v.x);
        float db = __fadd_rn(__fmaf_rn(m1, -2.0f, c), e2v.y);
        float dc = __fadd_rn(__fmaf_rn(m2, -2.0f, c), e2v.z);
        float dd = __fadd_rn(__fmaf_rn(m3, -2.0f, c), e2v.w);
        unsigned long long ka = ((unsigned long long)__float_as_uint(da) << 13) | (unsigned)k0;
        unsigned long long kb = ((unsigned long long)__float_as_uint(db) << 13) | (unsigned)(k0 + 1);
        unsigned long long kc = ((unsigned long long)__float_as_uint(dc) << 13) | (unsigned)(k0 + 2);
        unsigned long long kd = ((unsigned long long)__float_as_uint(dd) << 13) | (unsigned)(k0 + 3);
        ka = ka < kb ? ka : kb;
        kc = kc < kd ? kc : kd;
        ka = ka < kc ? ka : kc;
        key = key < ka ? key : ka;
    }
#pragma unroll
    for (int off = 16; off >= 1; off >>= 1) {
        unsigned long long o = __shfl_xor_sync(0xffffffffu, key, off);
        if (o < key) key = o;
    }
    int k = (int)(key & 0x1FFFull);

    // fused output: lanes 0..7; NO dynamic zv indexing — reload from global
    float s = 0.f;
    if (lane < 8) {
        float4 e  = ((const float4*)(emb + (size_t)k * CDIM))[lane];
        float4 zq = ((const float4*)(z + (size_t)row * CDIM))[lane];   // L1 hit
        float dx = __fadd_rn(e.x, -zq.x), dy = __fadd_rn(e.y, -zq.y);
        float dz = __fadd_rn(e.z, -zq.z), dw = __fadd_rn(e.w, -zq.w);
        float4 qv;
        qv.x = __fadd_rn(zq.x, dx); qv.y = __fadd_rn(zq.y, dy);
        qv.z = __fadd_rn(zq.z, dz); qv.w = __fadd_rn(zq.w, dw);
        ((float4*)(out + (size_t)row * CDIM))[lane] = qv;
        s = dx * dx + dy * dy + dz * dz + dw * dw;
        if (lane == 0) out[(size_t)N_ROWS * CDIM + 2 + row] = (float)k;
    }
#pragma unroll
    for (int off = 16; off >= 1; off >>= 1)
        s += __shfl_down_sync(0xffffffffu, s, off);
    if (lane == 0) warpsum[warp] = s;
    __syncthreads();
    if (warp == 0) {
        float v = (lane < 8) ? warpsum[lane] : 0.f;
#pragma unroll
        for (int off = 4; off >= 1; off >>= 1)
            v += __shfl_down_sync(0xffffffffu, v, off);
        if (lane == 0) d_partials[blockIdx.x] = v;
    }
}

// ---- final losses ---------------------------------------------------------
__global__ void vq_loss_kernel(float* __restrict__ out) {
    __shared__ float warpsum[32];
    int t = threadIdx.x;                 // 1024 threads, 4096 partials
    float s = d_partials[t] + d_partials[t + 1024]
            + d_partials[t + 2048] + d_partials[t + 3072];
    int lane = t & 31, wid = t >> 5;
#pragma unroll
    for (int o = 16; o > 0; o >>= 1)
        s += __shfl_down_sync(0xffffffffu, s, o);
    if (lane == 0) warpsum[wid] = s;
    __syncthreads();
    if (wid == 0) {
        float v = warpsum[lane];
#pragma unroll
        for (int o = 16; o > 0; o >>= 1)
            v += __shfl_down_sync(0xffffffffu, v, o);
        if (lane == 0) {
            float loss = v / (float)(N_ROWS * CDIM);
            out[(size_t)N_ROWS * CDIM + 0] = loss;   // vq_loss
            out[(size_t)N_ROWS * CDIM + 1] = loss;   // commitment_loss
        }
    }
}

// ---- entry ----------------------------------------------------------------
extern "C" void kernel_launch(void* const* d_in, const int* in_sizes, int n_in,
                              void* d_out, int out_size) {
    const float* z   = (const float*)d_in[0];
    const float* emb = (const float*)d_in[1];
    if (n_in >= 2 && in_sizes[0] == KCODES * CDIM && in_sizes[1] == N_ROWS * CDIM) {
        const float* t = z; z = emb; emb = t;
    }
    float* out = (float*)d_out;

    vq_prep<<<KCODES / 256 + N_ROWS / 256, 256>>>(emb, z);
    vq_filter<<<ROWBLK_F * NSPLIT_F, 256>>>();
    vq_resolve<<<N_ROWS / 8, 256>>>(z, emb, out);
    vq_loss_kernel<<<1, 1024>>>(out);
    (void)out_size;
}